// round 2
// baseline (speedup 1.0000x reference)
#include <cuda_runtime.h>

// ButterflyTransform: x[8192,4096] fp32, W[12,2048,2,2] fp32.
// All 12 layers use identical adjacent pairing -> per pair n the whole network
// is one composed 2x2 matrix M[n] = W0[n]@...@W11[n] (row-vector y = x*W).
// Phase 1: compose 2048 matrices (tiny). Phase 2: one streaming pass.
// Phase 2 is launched with Programmatic Dependent Launch so its prologue
// overlaps phase 1; it grid-dependency-syncs before touching g_M.

#define BATCH   8192
#define SIZE    4096
#define NPAIRS  (SIZE / 2)        // 2048
#define LOG_N   12
#define F4_PER_ROW (SIZE / 4)     // 1024 float4 per row

#define TPB     256
#define RB      8                 // rows per load batch (MLP)
#define STRIPS  (F4_PER_ROW / TPB)   // 4 column strips
#define BLOCKS_PER_STRIP 148
#define GRID    (STRIPS * BLOCKS_PER_STRIP)   // 592 = one full wave

// Composed matrices: (m00, m01, m10, m11) per pair. 32 KB scratch.
__device__ float4 g_M[NPAIRS];

__global__ void compose_kernel(const float* __restrict__ W) {
    int n = blockIdx.x * blockDim.x + threadIdx.x;
    if (n < NPAIRS) {
        const float4* Wl = reinterpret_cast<const float4*>(W);  // [l][n]
        float4 m = Wl[n];  // layer 0
#pragma unroll
        for (int l = 1; l < LOG_N; l++) {
            float4 w = Wl[l * NPAIRS + n];
            // M_new = M @ W_l  (row-vector composition)
            float4 t;
            t.x = fmaf(m.x, w.x, m.y * w.z);
            t.y = fmaf(m.x, w.y, m.y * w.w);
            t.z = fmaf(m.z, w.x, m.w * w.z);
            t.w = fmaf(m.z, w.y, m.w * w.w);
            m = t;
        }
        g_M[n] = m;
    }
#if __CUDA_ARCH__ >= 900
    cudaTriggerProgrammaticLaunchCompletion();
#endif
}

__global__ void __launch_bounds__(TPB, 4) apply_kernel(const float* __restrict__ x,
                                                       float* __restrict__ out) {
#if __CUDA_ARCH__ >= 900
    cudaGridDependencySynchronize();   // g_M must be visible before we read it
#endif
    const int strip  = blockIdx.x % STRIPS;
    const int bstart = blockIdx.x / STRIPS;       // 0..147
    const int col4   = strip * TPB + threadIdx.x; // 0..1023

    const float4 mA = g_M[2 * col4];
    const float4 mB = g_M[2 * col4 + 1];

    const float4* __restrict__ xin  = reinterpret_cast<const float4*>(x);
    float4* __restrict__       yout = reinterpret_cast<float4*>(out);

    const int NRB = BATCH / RB;                   // 1024 row batches
    for (int rb = bstart; rb < NRB; rb += BLOCKS_PER_STRIP) {
        long base = (long)rb * RB * F4_PER_ROW + col4;
        float4 v[RB];
#pragma unroll
        for (int r = 0; r < RB; r++)
            v[r] = xin[base + (long)r * F4_PER_ROW];
#pragma unroll
        for (int r = 0; r < RB; r++) {
            float4 o;
            o.x = fmaf(v[r].x, mA.x, v[r].y * mA.z);
            o.y = fmaf(v[r].x, mA.y, v[r].y * mA.w);
            o.z = fmaf(v[r].z, mB.x, v[r].w * mB.z);
            o.w = fmaf(v[r].z, mB.y, v[r].w * mB.w);
            yout[base + (long)r * F4_PER_ROW] = o;
        }
    }
}

extern "C" void kernel_launch(void* const* d_in, const int* in_sizes, int n_in,
                              void* d_out, int out_size) {
    const float* x = (const float*)d_in[0];   // [8192, 4096]
    const float* W = (const float*)d_in[1];   // [12, 2048, 2, 2]
    float* out = (float*)d_out;

    compose_kernel<<<NPAIRS / 256, 256>>>(W);

    cudaLaunchConfig_t cfg = {};
    cfg.gridDim  = dim3(GRID, 1, 1);
    cfg.blockDim = dim3(TPB, 1, 1);
    cfg.dynamicSmemBytes = 0;
    cfg.stream = 0;
    cudaLaunchAttribute attrs[1];
    attrs[0].id = cudaLaunchAttributeProgrammaticStreamSerialization;
    attrs[0].val.programmaticStreamSerializationAllowed = 1;
    cfg.attrs = attrs;
    cfg.numAttrs = 1;
    cudaLaunchKernelEx(&cfg, apply_kernel, x, out);
}